// round 3
// baseline (speedup 1.0000x reference)
#include <cuda_runtime.h>
#include <cuda_bf16.h>

// Problem: cummax along axis=2 of x[B=8, Tt=128, Ts=128, C=512] fp32.
// out[b,t,j,c] = max_{j'<=j} x[b,t,j',c]
//
// R2: float2 per thread (doubles thread count: 262144 threads, 1024 CTAs)
// to lift grid-limited occupancy 43% -> ~86%, plus streaming cache hints
// (__ldcs/__stcs) since every byte is touched exactly once.

static __device__ __forceinline__ float2 f2max(float2 a, float2 b) {
    float2 r;
    r.x = fmaxf(a.x, b.x);
    r.y = fmaxf(a.y, b.y);
    return r;
}

// B*Tt = 1024 rows, each row is [Ts=128, C=512].
// C/2 = 256 float2 per j. Columns total = 1024 * 256 = 262144 threads.
__global__ void __launch_bounds__(256, 8) cummax_kernel(
    const float2* __restrict__ in, float2* __restrict__ out)
{
    constexpr int TS = 128;
    constexpr int C2 = 256;               // 512 channels / 2
    const int col = blockIdx.x * blockDim.x + threadIdx.x;  // 0..262143
    const int bt  = col >> 8;             // which (b,t) row
    const int c2  = col & 255;            // which float2 within C

    const float2* __restrict__ p = in  + (size_t)bt * TS * C2 + c2;
    float2* __restrict__       q = out + (size_t)bt * TS * C2 + c2;

    float2 m = __ldcs(p);
    __stcs(q, m);

    // Unroll to expose independent loads (MLP) ahead of the serial max chain.
    #pragma unroll 8
    for (int j = 1; j < TS; ++j) {
        float2 v = __ldcs(p + (size_t)j * C2);
        m = f2max(m, v);
        __stcs(q + (size_t)j * C2, m);
    }
}

extern "C" void kernel_launch(void* const* d_in, const int* in_sizes, int n_in,
                              void* d_out, int out_size)
{
    const float2* x = (const float2*)d_in[0];
    float2* y = (float2*)d_out;

    // total float2 columns = 8*128 * (512/2) = 262144
    const int threads = 256;
    const int total_cols = 8 * 128 * (512 / 2);
    const int blocks = total_cols / threads;  // 1024
    cummax_kernel<<<blocks, threads>>>(x, y);
}